// round 15
// baseline (speedup 1.0000x reference)
#include <cuda_runtime.h>
#include <stdint.h>

#define TT 2048
#define BB 32
#define HH 512
#define NB 64
#define CPB 8

// SMEM byte offsets (dynamic smem)
#define SM_A   1024
#define SM_B   (SM_A + 131072)          // A: 32 rows x 4096B
#define SM_TOT (SM_B + 98304)           // B: 48 rows x 2048B  -> 230400 <= 232448

// scratch regions (flattened indices into the x-region bytes of A rows)
#define SX0 0
#define SX1 800
#define SH0 1600
#define SH1 2400

// ----------------------------------------------------------------------------
// Device scratch: h exchanged as bf16 hi/lo planes
// ----------------------------------------------------------------------------
__device__ __align__(16) unsigned short g_hh[2][2][BB * HH];
__device__ __align__(16) unsigned short g_hl[2][2][BB * HH];
__device__ unsigned g_grp[2][8];
__device__ unsigned g_root[2];
__device__ unsigned g_gen[2];

struct Args {
    const float* x;
    const float* Wxi[2][3];
    const float* Whh[2][3];
    const float* br[2];
    const float* bi[2];
    const float* bni[2];
    const float* bnh[2];
    float*       out;
};

// ----------------------------------------------------------------------------
// Helpers
// ----------------------------------------------------------------------------
__device__ __forceinline__ uint32_t smem_u32(const void* p_) {
    uint32_t a;
    asm("{ .reg .u64 t; cvta.to.shared.u64 t, %1; cvt.u32.u64 %0, t; }" : "=r"(a) : "l"(p_));
    return a;
}
__device__ __forceinline__ unsigned packbf(float lo, float hi) {
    unsigned d;
    asm("cvt.rn.bf16x2.f32 %0, %1, %2;" : "=r"(d) : "f"(hi), "f"(lo));
    return d;
}
__device__ __forceinline__ unsigned short cvtbf(float f) {
    unsigned short h;
    asm("cvt.rn.bf16.f32 %0, %1;" : "=h"(h) : "f"(f));
    return h;
}
__device__ __forceinline__ float lo16f(unsigned u) { return __uint_as_float(u << 16); }
__device__ __forceinline__ float hi16f(unsigned u) { return __uint_as_float(u & 0xffff0000u); }

__device__ __forceinline__ void split8(float4 a, float4 b, uint4& h, uint4& l) {
    h.x = packbf(a.x, a.y);  h.y = packbf(a.z, a.w);
    h.z = packbf(b.x, b.y);  h.w = packbf(b.z, b.w);
    l.x = packbf(a.x - lo16f(h.x), a.y - hi16f(h.x));
    l.y = packbf(a.z - lo16f(h.y), a.w - hi16f(h.y));
    l.z = packbf(b.x - lo16f(h.z), b.y - hi16f(h.z));
    l.w = packbf(b.z - lo16f(h.w), b.w - hi16f(h.w));
}

__device__ __forceinline__ unsigned atom_add_ar(unsigned* p_, unsigned v) {
    unsigned o;
    asm volatile("atom.acq_rel.gpu.add.u32 %0, [%1], %2;" : "=r"(o) : "l"(p_), "r"(v) : "memory");
    return o;
}
__device__ __forceinline__ unsigned ld_acq(const unsigned* p_) {
    unsigned v;
    asm volatile("ld.acquire.gpu.u32 %0, [%1];" : "=r"(v) : "l"(p_) : "memory");
    return v;
}
__device__ __forceinline__ void net_arrive(int d, int g) {
    unsigned a = atom_add_ar(&g_grp[d][g], 1u);
    if (((a + 1u) & 7u) == 0u) {
        unsigned r = atom_add_ar(&g_root[d], 1u);
        if (((r + 1u) & 7u) == 0u) atom_add_ar(&g_gen[d], 1u);
    }
}

__device__ __forceinline__ float fsig(float z) {
    return __fdividef(1.0f, 1.0f + __expf(-z));
}
__device__ __forceinline__ float ftanh(float z) {
    float a = fabsf(z), e = __expf(-2.0f * a);
    return copysignf(__fdividef(1.0f - e, 1.0f + e), z);
}

// scratch accessor: lives in x-region bytes [0,2048) of A rows 0..6
__device__ __forceinline__ float* scx(char* smem, int idx) {
    return (float*)(smem + SM_A + ((idx >> 9) << 12) + ((idx & 511) << 2));
}

// ldmatrix x4 (non-transposed, b16)
#define LDX4(R, ADDR)                                                           \
    asm volatile("ldmatrix.sync.aligned.m8n8.x4.shared.b16 {%0,%1,%2,%3}, [%4];" \
        : "=r"((R)[0]), "=r"((R)[1]), "=r"((R)[2]), "=r"((R)[3]) : "r"(ADDR))

// bf16 mma m16n8k16, fp32 accum
#define MMA4(C, A, B0, B1)                                                      \
    asm volatile("mma.sync.aligned.m16n8k16.row.col.f32.bf16.bf16.f32 "         \
        "{%0,%1,%2,%3}, {%4,%5,%6,%7}, {%8,%9}, {%0,%1,%2,%3};"                 \
        : "+f"((C)[0]), "+f"((C)[1]), "+f"((C)[2]), "+f"((C)[3])                \
        : "r"((A)[0]), "r"((A)[1]), "r"((A)[2]), "r"((A)[3]), "r"(B0), "r"(B1))

// ----------------------------------------------------------------------------
// Persistent fused GRU, warp-level tensor cores.
// A rows (K bf16): [x_hi 0..511 | x_lo 512..1023 | h_hi 1024..1535 | h_lo 1536..2047]
//   16B-chunk swizzle within row: phys_chunk = chunk ^ (row & 7)
// B rows n=0..47: n = gemm*24 + gate*8 + jl; row K: [W_hi 0..511 | W_lo 512..1023]
// Warp w: m-half = w&1, gemm = (w>>1)&1, k-half = w>>2; 3 n-tiles (gates)
// x warps (gemm=0) run MMA pre-wait; h warps (gemm=1) post-wait.
// ----------------------------------------------------------------------------
__global__ void __launch_bounds__(256, 1) gru_mma(Args p)
{
    extern __shared__ char smem[];
    const uint32_t su = smem_u32(smem);
    const int tid = threadIdx.x, wid = tid >> 5, lane = tid & 31;
    const int dir = blockIdx.x / NB, blk = blockIdx.x % NB, j0 = blk * CPB;

    // ---- weight prep (once): split-bf16, transposed [n][k], swizzled ----
    for (int idx = tid; idx < 48 * 512; idx += 256) {
        int n = idx >> 9, k = idx & 511;
        int g = n / 24, rem = n - g * 24, gate = rem >> 3, jl = rem & 7;
        const float* W = g ? p.Whh[dir][gate] : p.Wxi[dir][gate];
        float v = W[(size_t)k * HH + j0 + jl];
        unsigned short hb = cvtbf(v);
        unsigned short lb = cvtbf(v - __uint_as_float((unsigned)hb << 16));
        char* rowp = smem + SM_B + n * 2048;
        int ib = (k & 7) * 2, x7 = n & 7;
        *(unsigned short*)(rowp + (((k >> 3) ^ x7) << 4) + ib) = hb;
        *(unsigned short*)(rowp + ((((512 + k) >> 3) ^ x7) << 4) + ib) = lb;
    }

    // ---- warp slice setup ----
    const int m0 = (wid & 1) * 16;
    const int g2 = (wid >> 1) & 1;
    const int kh = wid >> 2;
    const int rA = m0 + (lane & 7) + ((lane >> 3) & 1) * 8;
    const uint32_t aXor = (uint32_t)(rA & 7);
    const uint32_t aRow = su + SM_A + (uint32_t)rA * 4096u;
    const uint32_t kcA = (uint32_t)(lane >> 4);
    const uint32_t bXor = (uint32_t)(lane & 7);
    const uint32_t kcB = (uint32_t)(lane >> 3);
    const uint32_t bR0 = su + SM_B + (uint32_t)(g2 * 24 + 0 + (lane & 7)) * 2048u;
    const uint32_t bR1 = su + SM_B + (uint32_t)(g2 * 24 + 8 + (lane & 7)) * 2048u;
    const uint32_t bR2 = su + SM_B + (uint32_t)(g2 * 24 + 16 + (lane & 7)) * 2048u;
    const int aHi = g2 * 1024;

    // scratch region for this warp's partials
    const int scrBase = g2 ? (kh ? SH1 : SH0) : (kh ? SX1 : SX0);
    const int brow = m0 + (lane >> 2);
    const int cc = (lane & 3) * 2;

    // ---- warp0 epilogue state ----
    float cbr[8], cbi[8], cbni[8], cbnh[8], hprev[8];
    #pragma unroll
    for (int jl = 0; jl < 8; ++jl) hprev[jl] = 0.0f;
    if (wid == 0) {
        #pragma unroll
        for (int jl = 0; jl < 8; ++jl) {
            cbr[jl]  = __ldg(&p.br [dir][j0 + jl]);
            cbi[jl]  = __ldg(&p.bi [dir][j0 + jl]);
            cbni[jl] = __ldg(&p.bni[dir][j0 + jl]);
            cbnh[jl] = __ldg(&p.bnh[dir][j0 + jl]);
        }
    }

    // ---- h0 = 0 planes + initial arrive ----
    unsigned base = 0;
    if (tid == 0) base = ld_acq(&g_gen[dir]);
    if (tid < BB) {
        uint4 z = make_uint4(0u, 0u, 0u, 0u);
        *(uint4*)&g_hh[dir][0][tid * HH + j0] = z;
        *(uint4*)&g_hl[dir][0][tid * HH + j0] = z;
    }
    __syncthreads();
    if (tid == 0) net_arrive(dir, blk >> 3);

    float* out = p.out;

#define SEGRUN(AOFF, BOFF, D0, D1)                                              \
    _Pragma("unroll 4")                                                         \
    for (int dd = (D0); dd < (D1); ++dd) {                                      \
        uint32_t ca = (uint32_t)((((AOFF) + dd * 32) >> 3)) + kcA;              \
        uint32_t cb = (uint32_t)((((BOFF) + dd * 32) >> 3)) + kcB;              \
        uint32_t fa0[4], fa1[4], fb0[4], fb1[4], fb2[4];                        \
        LDX4(fa0, aRow + ((ca ^ aXor) << 4));                                   \
        LDX4(fa1, aRow + (((ca + 2) ^ aXor) << 4));                             \
        LDX4(fb0, bR0 + ((cb ^ bXor) << 4));                                    \
        LDX4(fb1, bR1 + ((cb ^ bXor) << 4));                                    \
        LDX4(fb2, bR2 + ((cb ^ bXor) << 4));                                    \
        MMA4(acc0, fa0, fb0[0], fb0[1]);                                        \
        MMA4(acc1, fa0, fb1[0], fb1[1]);                                        \
        MMA4(acc2, fa0, fb2[0], fb2[1]);                                        \
        MMA4(acc0, fa1, fb0[2], fb0[3]);                                        \
        MMA4(acc1, fa1, fb1[2], fb1[3]);                                        \
        MMA4(acc2, fa1, fb2[2], fb2[3]);                                        \
    }

    for (int st = 0; st < TT; ++st) {
        const int t = dir ? (TT - 1 - st) : st;
        const int par = st & 1;

        // 1. stage x(t): fp32 -> split-bf16 -> A x regions (barrier shadow)
        {
            const float* xb = p.x + (size_t)t * (BB * HH);
            #pragma unroll 4
            for (int i = 0; i < 8; ++i) {
                int id = tid + i * 256;
                int row = id >> 6, c8 = id & 63, x7 = row & 7;
                const float4* sp = (const float4*)(xb + row * HH + c8 * 8);
                float4 a = __ldg(sp), b = __ldg(sp + 1);
                uint4 h4, l4;
                split8(a, b, h4, l4);
                char* rowp = smem + SM_A + row * 4096;
                *(uint4*)(rowp + ((c8 ^ x7) << 4)) = h4;
                *(uint4*)(rowp + (((c8 + 64) ^ x7) << 4)) = l4;
            }
        }
        __syncthreads();

        // 2. x-MMA pre-wait (x warps), 3-term split chains
        float acc0[4] = {0.f, 0.f, 0.f, 0.f};
        float acc1[4] = {0.f, 0.f, 0.f, 0.f};
        float acc2[4] = {0.f, 0.f, 0.f, 0.f};
        if (g2 == 0) {
            if (kh == 0) { SEGRUN(0, 0, 0, 16)  SEGRUN(0, 512, 0, 8) }
            else         { SEGRUN(0, 512, 8, 16)  SEGRUN(512, 0, 0, 16) }
        }

        // 3. wait for h(st)
        if (tid == 0) { while (ld_acq(&g_gen[dir]) - base < (unsigned)(st + 1)) { } }
        __syncthreads();

        // 4. stage h planes -> A h regions (all threads, raw swizzled copies)
        {
            const unsigned short* hhp = g_hh[dir][par];
            const unsigned short* hlp = g_hl[dir][par];
            #pragma unroll 4
            for (int i = 0; i < 8; ++i) {
                int id = tid + i * 256;
                int row = id >> 6, c8 = id & 63, x7 = row & 7;
                char* rowp = smem + SM_A + row * 4096;
                uint4 v = __ldcv((const uint4*)(hhp + row * HH + c8 * 8));
                *(uint4*)(rowp + (((c8 + 128) ^ x7) << 4)) = v;
                uint4 v2 = __ldcv((const uint4*)(hlp + row * HH + c8 * 8));
                *(uint4*)(rowp + (((c8 + 192) ^ x7) << 4)) = v2;
            }
        }
        __syncthreads();

        // 5. h warps: MMA then scratch write. x warps: scratch write (overlapped).
        if (g2 == 1) {
            if (kh == 0) { SEGRUN(aHi, 0, 0, 16)  SEGRUN(aHi, 512, 0, 8) }
            else         { SEGRUN(aHi, 512, 8, 16)  SEGRUN(aHi + 512, 0, 0, 16) }
        }
        {
            #pragma unroll
            for (int gt = 0; gt < 3; ++gt) {
                float* a4 = (gt == 0) ? acc0 : (gt == 1) ? acc1 : acc2;
                *scx(smem, scrBase + brow * 25 + gt * 8 + cc)           = a4[0];
                *scx(smem, scrBase + brow * 25 + gt * 8 + cc + 1)       = a4[1];
                *scx(smem, scrBase + (brow + 8) * 25 + gt * 8 + cc)     = a4[2];
                *scx(smem, scrBase + (brow + 8) * 25 + gt * 8 + cc + 1) = a4[3];
            }
        }
        __syncthreads();

        // 6. epilogue (warp 0; lane = batch row): 4-way scratch add + gates
        if (wid == 0) {
            float hn[8];
            #pragma unroll
            for (int jl = 0; jl < 8; ++jl) {
                int bx = lane * 25 + jl;
                float axr = *scx(smem, SX0 + bx)      + *scx(smem, SX1 + bx);
                float axc = *scx(smem, SX0 + bx + 8)  + *scx(smem, SX1 + bx + 8);
                float axn = *scx(smem, SX0 + bx + 16) + *scx(smem, SX1 + bx + 16);
                float ahr = *scx(smem, SH0 + bx)      + *scx(smem, SH1 + bx);
                float ahc = *scx(smem, SH0 + bx + 8)  + *scx(smem, SH1 + bx + 8);
                float ahn = *scx(smem, SH0 + bx + 16) + *scx(smem, SH1 + bx + 16);
                float r = fsig(axr + ahr + cbr[jl]);
                float c = fsig(axc + ahc + cbi[jl]);
                float n = ftanh(axn + cbni[jl] + r * (ahn + cbnh[jl]));
                hn[jl] = n + c * (hprev[jl] - n);
                hprev[jl] = hn[jl];
            }
            float4 q0 = make_float4(hn[0], hn[1], hn[2], hn[3]);
            float4 q1 = make_float4(hn[4], hn[5], hn[6], hn[7]);
            uint4 h4, l4;
            split8(q0, q1, h4, l4);
            *(uint4*)&g_hh[dir][par ^ 1][lane * HH + j0] = h4;
            *(uint4*)&g_hl[dir][par ^ 1][lane * HH + j0] = l4;
            float* op = out + ((size_t)t * BB + lane) * (2 * HH) + dir * HH + j0;
            *(float4*)op = q0;
            *(float4*)(op + 4) = q1;
        }
        __syncthreads();
        if (tid == 0) net_arrive(dir, blk >> 3);
    }
#undef SEGRUN
}

// ----------------------------------------------------------------------------
// Launch. Input order: x, Wri_f,Wci_f,Wni_f,Wrh_f,Wch_f,Wnh_f,br_f,bi_f,bni_f,
// bnh_f, Wri_b,Wci_b,Wni_b,Wrh_b,Wch_b,Wnh_b,br_b,bi_b,bni_b,bnh_b
// ----------------------------------------------------------------------------
extern "C" void kernel_launch(void* const* d_in, const int* in_sizes, int n_in,
                              void* d_out, int out_size)
{
    (void)in_sizes; (void)n_in; (void)out_size;
    Args a;
    a.x = (const float*)d_in[0];
    a.Wxi[0][0] = (const float*)d_in[1];
    a.Wxi[0][1] = (const float*)d_in[2];
    a.Wxi[0][2] = (const float*)d_in[3];
    a.Whh[0][0] = (const float*)d_in[4];
    a.Whh[0][1] = (const float*)d_in[5];
    a.Whh[0][2] = (const float*)d_in[6];
    a.br [0] = (const float*)d_in[7];
    a.bi [0] = (const float*)d_in[8];
    a.bni[0] = (const float*)d_in[9];
    a.bnh[0] = (const float*)d_in[10];
    a.Wxi[1][0] = (const float*)d_in[11];
    a.Wxi[1][1] = (const float*)d_in[12];
    a.Wxi[1][2] = (const float*)d_in[13];
    a.Whh[1][0] = (const float*)d_in[14];
    a.Whh[1][1] = (const float*)d_in[15];
    a.Whh[1][2] = (const float*)d_in[16];
    a.br [1] = (const float*)d_in[17];
    a.bi [1] = (const float*)d_in[18];
    a.bni[1] = (const float*)d_in[19];
    a.bnh[1] = (const float*)d_in[20];
    a.out = (float*)d_out;

    cudaFuncSetAttribute(gru_mma, cudaFuncAttributeMaxDynamicSharedMemorySize, SM_TOT);
    gru_mma<<<2 * NB, 256, SM_TOT>>>(a);
}

// round 16
// speedup vs baseline: 1.3260x; 1.3260x over previous
#include <cuda_runtime.h>
#include <stdint.h>

#define TT 2048
#define BB 32
#define HH 512
#define NB 64
#define CPB 8

// SMEM byte offsets (dynamic smem)
#define SM_A   1024
#define SM_B   (SM_A + 131072)          // A: 32 rows x 4096B
#define SM_TOT (SM_B + 98304)           // B: 48 rows x 2048B  -> 230400 <= 232448

// scratch regions (flattened float indices into the x-region bytes of A rows 0..6)
#define SX0 0
#define SX1 800
#define SH0 1600
#define SH1 2400

// ----------------------------------------------------------------------------
// Device scratch: h exchanged as bf16 hi/lo planes
// ----------------------------------------------------------------------------
__device__ __align__(16) unsigned short g_hh[2][2][BB * HH];
__device__ __align__(16) unsigned short g_hl[2][2][BB * HH];
__device__ unsigned g_grp[2][8];
__device__ unsigned g_root[2];

struct Args {
    const float* x;
    const float* Wxi[2][3];
    const float* Whh[2][3];
    const float* br[2];
    const float* bi[2];
    const float* bni[2];
    const float* bnh[2];
    float*       out;
};

// ----------------------------------------------------------------------------
// Helpers
// ----------------------------------------------------------------------------
__device__ __forceinline__ uint32_t smem_u32(const void* p_) {
    uint32_t a;
    asm("{ .reg .u64 t; cvta.to.shared.u64 t, %1; cvt.u32.u64 %0, t; }" : "=r"(a) : "l"(p_));
    return a;
}
__device__ __forceinline__ unsigned packbf(float lo, float hi) {
    unsigned d;
    asm("cvt.rn.bf16x2.f32 %0, %1, %2;" : "=r"(d) : "f"(hi), "f"(lo));
    return d;
}
__device__ __forceinline__ unsigned short cvtbf(float f) {
    unsigned short h;
    asm("cvt.rn.bf16.f32 %0, %1;" : "=h"(h) : "f"(f));
    return h;
}
__device__ __forceinline__ float lo16f(unsigned u) { return __uint_as_float(u << 16); }
__device__ __forceinline__ float hi16f(unsigned u) { return __uint_as_float(u & 0xffff0000u); }

__device__ __forceinline__ void split8(float4 a, float4 b, uint4& h, uint4& l) {
    h.x = packbf(a.x, a.y);  h.y = packbf(a.z, a.w);
    h.z = packbf(b.x, b.y);  h.w = packbf(b.z, b.w);
    l.x = packbf(a.x - lo16f(h.x), a.y - hi16f(h.x));
    l.y = packbf(a.z - lo16f(h.y), a.w - hi16f(h.y));
    l.z = packbf(b.x - lo16f(h.z), b.y - hi16f(h.z));
    l.w = packbf(b.z - lo16f(h.w), b.w - hi16f(h.w));
}

__device__ __forceinline__ unsigned atom_add_ar(unsigned* p_, unsigned v) {
    unsigned o;
    asm volatile("atom.acq_rel.gpu.add.u32 %0, [%1], %2;" : "=r"(o) : "l"(p_), "r"(v) : "memory");
    return o;
}
__device__ __forceinline__ unsigned ld_acq(const unsigned* p_) {
    unsigned v;
    asm volatile("ld.acquire.gpu.u32 %0, [%1];" : "=r"(v) : "l"(p_) : "memory");
    return v;
}
// Two-level arrive: leaf (8 CTAs) then root. Release condition: root advances
// by 8 per completed round (root hits 8n only once ALL leaves completed n).
__device__ __forceinline__ void net_arrive(int d, int g) {
    unsigned a = atom_add_ar(&g_grp[d][g], 1u);
    if (((a + 1u) & 7u) == 0u) atom_add_ar(&g_root[d], 1u);
}

__device__ __forceinline__ float fsig(float z) {
    return __fdividef(1.0f, 1.0f + __expf(-z));
}
__device__ __forceinline__ float ftanh(float z) {
    float a = fabsf(z), e = __expf(-2.0f * a);
    return copysignf(__fdividef(1.0f - e, 1.0f + e), z);
}

// scratch accessor: lives in x-region bytes [0,2048) of A rows 0..6
__device__ __forceinline__ float* scx(char* smem, int idx) {
    return (float*)(smem + SM_A + ((idx >> 9) << 12) + ((idx & 511) << 2));
}

// ldmatrix x4 (non-transposed, b16)
#define LDX4(R, ADDR)                                                           \
    asm volatile("ldmatrix.sync.aligned.m8n8.x4.shared.b16 {%0,%1,%2,%3}, [%4];" \
        : "=r"((R)[0]), "=r"((R)[1]), "=r"((R)[2]), "=r"((R)[3]) : "r"(ADDR))

// bf16 mma m16n8k16, fp32 accum
#define MMA4(C, A, B0, B1)                                                      \
    asm volatile("mma.sync.aligned.m16n8k16.row.col.f32.bf16.bf16.f32 "         \
        "{%0,%1,%2,%3}, {%4,%5,%6,%7}, {%8,%9}, {%0,%1,%2,%3};"                 \
        : "+f"((C)[0]), "+f"((C)[1]), "+f"((C)[2]), "+f"((C)[3])                \
        : "r"((A)[0]), "r"((A)[1]), "r"((A)[2]), "r"((A)[3]), "r"(B0), "r"(B1))

// ----------------------------------------------------------------------------
// Persistent fused GRU, warp-level tensor cores (R13 skeleton).
// A rows (K bf16): [x_hi 0..511 | x_lo 512..1023 | h_hi 1024..1535 | h_lo 1536..2047]
//   16B-chunk swizzle within row: phys_chunk = chunk ^ (row & 7)
// B rows n=0..47: n = gemm*24 + gate*8 + jl; row K: [W_hi 0..511 | W_lo 512..1023]
// Warp w: m-half = w&1, gemm = (w>>1)&1, k-half = w>>2; 3 n-tiles (gates).
// All warps run MMA concurrently post-wait (2 warps/SMSP covering latency).
// ----------------------------------------------------------------------------
__global__ void __launch_bounds__(256, 1) gru_mma(Args p)
{
    extern __shared__ char smem[];
    const uint32_t su = smem_u32(smem);
    const int tid = threadIdx.x, wid = tid >> 5, lane = tid & 31;
    const int dir = blockIdx.x / NB, blk = blockIdx.x % NB, j0 = blk * CPB;

    // ---- weight prep (once): split-bf16, transposed [n][k], swizzled ----
    for (int idx = tid; idx < 48 * 512; idx += 256) {
        int n = idx >> 9, k = idx & 511;
        int g = n / 24, rem = n - g * 24, gate = rem >> 3, jl = rem & 7;
        const float* W = g ? p.Whh[dir][gate] : p.Wxi[dir][gate];
        float v = W[(size_t)k * HH + j0 + jl];
        unsigned short hb = cvtbf(v);
        unsigned short lb = cvtbf(v - __uint_as_float((unsigned)hb << 16));
        char* rowp = smem + SM_B + n * 2048;
        int ib = (k & 7) * 2, x7 = n & 7;
        *(unsigned short*)(rowp + (((k >> 3) ^ x7) << 4) + ib) = hb;
        *(unsigned short*)(rowp + ((((512 + k) >> 3) ^ x7) << 4) + ib) = lb;
    }

    // ---- warp slice setup ----
    const int m0 = (wid & 1) * 16;
    const int g2 = (wid >> 1) & 1;
    const int kh = wid >> 2;
    const int rA = m0 + (lane & 7) + ((lane >> 3) & 1) * 8;
    const uint32_t aXor = (uint32_t)(rA & 7);
    const uint32_t aRow = su + SM_A + (uint32_t)rA * 4096u;
    const uint32_t kcA = (uint32_t)(lane >> 4);
    const uint32_t bXor = (uint32_t)(lane & 7);
    const uint32_t kcB = (uint32_t)(lane >> 3);
    const uint32_t bR0 = su + SM_B + (uint32_t)(g2 * 24 + 0 + (lane & 7)) * 2048u;
    const uint32_t bR1 = su + SM_B + (uint32_t)(g2 * 24 + 8 + (lane & 7)) * 2048u;
    const uint32_t bR2 = su + SM_B + (uint32_t)(g2 * 24 + 16 + (lane & 7)) * 2048u;
    const int aHi = g2 * 1024;

    // scratch region + in-region coordinates for this warp's partial stores
    const int scrBase = g2 ? (kh ? SH1 : SH0) : (kh ? SX1 : SX0);
    const int brow = m0 + (lane >> 2);
    const int cc = (lane & 3) * 2;

    // ---- per-thread epilogue state: thread owns (b = tid>>3, jl = tid&7) ----
    const int eb = tid >> 3;
    const int ejl = tid & 7;
    const float cbr  = __ldg(&p.br [dir][j0 + ejl]);
    const float cbi  = __ldg(&p.bi [dir][j0 + ejl]);
    const float cbni = __ldg(&p.bni[dir][j0 + ejl]);
    const float cbnh = __ldg(&p.bnh[dir][j0 + ejl]);
    float hprev = 0.0f;

    // ---- h0 = 0 planes + initial arrive ----
    unsigned base = 0;
    if (tid == 0) base = ld_acq(&g_root[dir]);
    if (tid < BB) {
        uint4 z = make_uint4(0u, 0u, 0u, 0u);
        *(uint4*)&g_hh[dir][0][tid * HH + j0] = z;
        *(uint4*)&g_hl[dir][0][tid * HH + j0] = z;
    }
    __syncthreads();
    if (tid == 0) net_arrive(dir, blk >> 3);

    float* out = p.out;

#define SEGRUN(AOFF, BOFF, D0, D1)                                              \
    _Pragma("unroll")                                                           \
    for (int dd = (D0); dd < (D1); ++dd) {                                      \
        uint32_t ca = (uint32_t)((((AOFF) + dd * 32) >> 3)) + kcA;              \
        uint32_t cb = (uint32_t)((((BOFF) + dd * 32) >> 3)) + kcB;              \
        uint32_t fa0[4], fa1[4], fb0[4], fb1[4], fb2[4];                        \
        LDX4(fa0, aRow + ((ca ^ aXor) << 4));                                   \
        LDX4(fa1, aRow + (((ca + 2) ^ aXor) << 4));                             \
        LDX4(fb0, bR0 + ((cb ^ bXor) << 4));                                    \
        LDX4(fb1, bR1 + ((cb ^ bXor) << 4));                                    \
        LDX4(fb2, bR2 + ((cb ^ bXor) << 4));                                    \
        MMA4(acc0, fa0, fb0[0], fb0[1]);                                        \
        MMA4(acc1, fa0, fb1[0], fb1[1]);                                        \
        MMA4(acc2, fa0, fb2[0], fb2[1]);                                        \
        MMA4(acc0, fa1, fb0[2], fb0[3]);                                        \
        MMA4(acc1, fa1, fb1[2], fb1[3]);                                        \
        MMA4(acc2, fa1, fb2[2], fb2[3]);                                        \
    }

    for (int st = 0; st < TT; ++st) {
        const int t = dir ? (TT - 1 - st) : st;
        const int par = st & 1;

        // 1. stage x(t): fp32 -> split-bf16 -> A x regions (overlaps tid0's poll)
        {
            const float* xb = p.x + (size_t)t * (BB * HH);
            #pragma unroll 4
            for (int i = 0; i < 8; ++i) {
                int id = tid + i * 256;
                int row = id >> 6, c8 = id & 63, x7 = row & 7;
                const float4* sp = (const float4*)(xb + row * HH + c8 * 8);
                float4 a = __ldg(sp), b = __ldg(sp + 1);
                uint4 h4, l4;
                split8(a, b, h4, l4);
                char* rowp = smem + SM_A + row * 4096;
                *(uint4*)(rowp + ((c8 ^ x7) << 4)) = h4;
                *(uint4*)(rowp + (((c8 + 64) ^ x7) << 4)) = l4;
            }
        }

        // 2. wait for h(st): poll root (advances by 8 per completed round)
        if (tid == 0) {
            unsigned tgt = (unsigned)(8 * (st + 1));
            while (ld_acq(&g_root[dir]) - base < tgt) { }
        }
        __syncthreads();                       // S1: x staged + h globally ready

        // 3. stage h planes -> A h regions (raw swizzled copies)
        {
            const unsigned short* hhp = g_hh[dir][par];
            const unsigned short* hlp = g_hl[dir][par];
            #pragma unroll 4
            for (int i = 0; i < 8; ++i) {
                int id = tid + i * 256;
                int row = id >> 6, c8 = id & 63, x7 = row & 7;
                char* rowp = smem + SM_A + row * 4096;
                uint4 v = __ldcv((const uint4*)(hhp + row * HH + c8 * 8));
                *(uint4*)(rowp + (((c8 + 128) ^ x7) << 4)) = v;
                uint4 v2 = __ldcv((const uint4*)(hlp + row * HH + c8 * 8));
                *(uint4*)(rowp + (((c8 + 192) ^ x7) << 4)) = v2;
            }
        }
        __syncthreads();                       // S2: A complete

        // 4. MMA phase: all 8 warps in parallel (x- and h-gemm), 3-term split
        float acc0[4] = {0.f, 0.f, 0.f, 0.f};
        float acc1[4] = {0.f, 0.f, 0.f, 0.f};
        float acc2[4] = {0.f, 0.f, 0.f, 0.f};
        if (kh == 0) { SEGRUN(aHi, 0, 0, 16)  SEGRUN(aHi, 512, 0, 8) }
        else         { SEGRUN(aHi, 512, 8, 16)  SEGRUN(aHi + 512, 0, 0, 16) }
        __syncthreads();                       // S3: all A reads done

        // 5. one-pass partial store to this warp's own scratch region
        #pragma unroll
        for (int gt = 0; gt < 3; ++gt) {
            float* a4 = (gt == 0) ? acc0 : (gt == 1) ? acc1 : acc2;
            *scx(smem, scrBase + brow * 25 + gt * 8 + cc)           = a4[0];
            *scx(smem, scrBase + brow * 25 + gt * 8 + cc + 1)       = a4[1];
            *scx(smem, scrBase + (brow + 8) * 25 + gt * 8 + cc)     = a4[2];
            *scx(smem, scrBase + (brow + 8) * 25 + gt * 8 + cc + 1) = a4[3];
        }
        __syncthreads();                       // S4: scratch complete

        // 6. distributed epilogue: every thread computes its (b, jl) output
        {
            const int bx = eb * 25 + ejl;
            float axr = *scx(smem, SX0 + bx)      + *scx(smem, SX1 + bx);
            float axc = *scx(smem, SX0 + bx + 8)  + *scx(smem, SX1 + bx + 8);
            float axn = *scx(smem, SX0 + bx + 16) + *scx(smem, SX1 + bx + 16);
            float ahr = *scx(smem, SH0 + bx)      + *scx(smem, SH1 + bx);
            float ahc = *scx(smem, SH0 + bx + 8)  + *scx(smem, SH1 + bx + 8);
            float ahn = *scx(smem, SH0 + bx + 16) + *scx(smem, SH1 + bx + 16);
            float r = fsig(axr + ahr + cbr);
            float c = fsig(axc + ahc + cbi);
            float n = ftanh(axn + cbni + r * (ahn + cbnh));
            float hn = n + c * (hprev - n);
            hprev = hn;
            unsigned short hb = cvtbf(hn);
            unsigned short lb = cvtbf(hn - __uint_as_float((unsigned)hb << 16));
            g_hh[dir][par ^ 1][eb * HH + j0 + ejl] = hb;
            g_hl[dir][par ^ 1][eb * HH + j0 + ejl] = lb;
            out[((size_t)t * BB + eb) * (2 * HH) + dir * HH + j0 + ejl] = hn;
        }
        __syncthreads();                       // S5: stores ordered before arrive
        if (tid == 0) net_arrive(dir, blk >> 3);
    }
#undef SEGRUN
}

// ----------------------------------------------------------------------------
// Launch. Input order: x, Wri_f,Wci_f,Wni_f,Wrh_f,Wch_f,Wnh_f,br_f,bi_f,bni_f,
// bnh_f, Wri_b,Wci_b,Wni_b,Wrh_b,Wch_b,Wnh_b,br_b,bi_b,bni_b,bnh_b
// ----------------------------------------------------------------------------
extern "C" void kernel_launch(void* const* d_in, const int* in_sizes, int n_in,
                              void* d_out, int out_size)
{
    (void)in_sizes; (void)n_in; (void)out_size;
    Args a;
    a.x = (const float*)d_in[0];
    a.Wxi[0][0] = (const float*)d_in[1];
    a.Wxi[0][1] = (const float*)d_in[2];
    a.Wxi[0][2] = (const float*)d_in[3];
    a.Whh[0][0] = (const float*)d_in[4];
    a.Whh[0][1] = (const float*)d_in[5];
    a.Whh[0][2] = (const float*)d_in[6];
    a.br [0] = (const float*)d_in[7];
    a.bi [0] = (const float*)d_in[8];
    a.bni[0] = (const float*)d_in[9];
    a.bnh[0] = (const float*)d_in[10];
    a.Wxi[1][0] = (const float*)d_in[11];
    a.Wxi[1][1] = (const float*)d_in[12];
    a.Wxi[1][2] = (const float*)d_in[13];
    a.Whh[1][0] = (const float*)d_in[14];
    a.Whh[1][1] = (const float*)d_in[15];
    a.Whh[1][2] = (const float*)d_in[16];
    a.br [1] = (const float*)d_in[17];
    a.bi [1] = (const float*)d_in[18];
    a.bni[1] = (const float*)d_in[19];
    a.bnh[1] = (const float*)d_in[20];
    a.out = (float*)d_out;

    cudaFuncSetAttribute(gru_mma, cudaFuncAttributeMaxDynamicSharedMemorySize, SM_TOT);
    gru_mma<<<2 * NB, 256, SM_TOT>>>(a);
}